// round 1
// baseline (speedup 1.0000x reference)
#include <cuda_runtime.h>
#include <cuda_bf16.h>

// Problem: B=500000, F=32, U=48, S=1000, H=24
// inputs[B,32], ids[B], state[S,48], gru_kernel[32,144], gru_rec_kernel[48,144],
// gru_bias[144], dense_w[80,24], dense_b[24], out_w[24,1], out_b[1]
// Output: concat( out[B,1], new_state[S,48] )  -> float32, 548000 elems

#define ULL unsigned long long

__device__ float g_G[1000 * 144];   // precomputed state @ gru_rec_kernel
__device__ int   g_winner[1000];    // last (max) row index writing each slot

// ---------- packed f32x2 helpers ----------
__device__ __forceinline__ ULL pk2(float lo, float hi) {
    ULL r; asm("mov.b64 %0, {%1, %2};" : "=l"(r) : "f"(lo), "f"(hi)); return r;
}
__device__ __forceinline__ float2 up2(ULL v) {
    float2 r; asm("mov.b64 {%0, %1}, %2;" : "=f"(r.x), "=f"(r.y) : "l"(v)); return r;
}
__device__ __forceinline__ ULL fma2(ULL a, ULL b, ULL c) {
    ULL d; asm("fma.rn.f32x2 %0, %1, %2, %3;" : "=l"(d) : "l"(a), "l"(b), "l"(c)); return d;
}
__device__ __forceinline__ float hsum2(ULL v) { float2 f = up2(v); return f.x + f.y; }

__device__ __forceinline__ float sigmoidf(float x) {
    return __fdividef(1.0f, 1.0f + __expf(-x));
}
__device__ __forceinline__ float tanh_fast(float x) {
    // tanh(x) = 2*sigmoid(2x)-1 ; __expf/__fdividef err ~2^-21, fine for 1e-3
    return fmaf(2.0f, __fdividef(1.0f, 1.0f + __expf(-2.0f * x)), -1.0f);
}

// ---------- kernel 0: precompute G = state @ U_rec, copy state->out_state, init winner ----------
__global__ void prep_kernel(const float* __restrict__ state,
                            const float* __restrict__ Urec,
                            float* __restrict__ out_state) {
    int s = blockIdx.x;      // 0..S-1
    int j = threadIdx.x;     // 0..143
    __shared__ float hs[48];
    if (j < 48) {
        float v = state[s * 48 + j];
        hs[j] = v;
        out_state[s * 48 + j] = v;   // default: unchanged slots keep old state
    }
    if (j == 0) g_winner[s] = -1;
    __syncthreads();
    float acc = 0.0f;
    #pragma unroll
    for (int u = 0; u < 48; u++)
        acc = fmaf(hs[u], Urec[u * 144 + j], acc);
    g_G[s * 144 + j] = acc;
}

// ---------- kernel 1: winner[s] = max b with ids[b]==s (last-wins scatter) ----------
__global__ void argmax_kernel(const int* __restrict__ ids, int B) {
    int b = blockIdx.x * blockDim.x + threadIdx.x;
    if (b < B) atomicMax(&g_winner[ids[b]], b);
}

// ---------- kernel 2: main fused GRU + MLP head ----------
__global__ void __launch_bounds__(96)
main_kernel(const float* __restrict__ inputs,
            const int*   __restrict__ ids,
            const float* __restrict__ state,
            const float* __restrict__ Wk,      // [32,144]
            const float* __restrict__ gbias,   // [144]
            const float* __restrict__ Dw,      // [80,24]
            const float* __restrict__ Db,      // [24]
            const float* __restrict__ Ow,      // [24]
            const float* __restrict__ Ob,      // [1]
            float* __restrict__ out,           // [B]
            float* __restrict__ out_state,     // [S,48]
            int B) {
    // Transposed weights in shared (row-major per output unit -> contiguous pairs)
    __shared__ __align__(16) float sW[144 * 32];  // sW[j*32+f] = Wk[f,j]
    __shared__ __align__(16) float sD[24 * 80];   // sD[j*80+c] = Dw[c,j]
    __shared__ float sB[144];
    __shared__ float sDb[24];
    __shared__ float sOw[24];
    __shared__ float sOb;
    __shared__ ULL   hsh[24 * 96];                // packed h_new pairs per thread

    const int tid = threadIdx.x;

    for (int i = tid; i < 144 * 32; i += 96) {
        int j = i >> 5, f = i & 31;
        sW[i] = Wk[f * 144 + j];
    }
    for (int i = tid; i < 24 * 80; i += 96) {
        int j = i / 80, c = i - j * 80;
        sD[i] = Dw[c * 24 + j];
    }
    for (int i = tid; i < 144; i += 96) sB[i] = gbias[i];
    if (tid < 24) { sDb[tid] = Db[tid]; sOw[tid] = Ow[tid]; }
    if (tid == 0) sOb = Ob[0];
    __syncthreads();

    const int b = blockIdx.x * 96 + tid;
    if (b >= B) return;

    // load x row as 16 packed pairs
    ULL x2[16];
    const float4* xr = (const float4*)(inputs + (size_t)b * 32);
    #pragma unroll
    for (int k = 0; k < 8; k++) {
        float4 v = xr[k];
        x2[2 * k]     = pk2(v.x, v.y);
        x2[2 * k + 1] = pk2(v.z, v.w);
    }

    const int id = ids[b];
    const float* Gp = g_G + id * 144;
    const float* hp = state + id * 48;

    // GRU units, two at a time -> packed h_new into shared
    for (int u2 = 0; u2 < 24; u2++) {
        float h01[2];
        #pragma unroll
        for (int p = 0; p < 2; p++) {
            const int u = 2 * u2 + p;
            const ULL* wz = (const ULL*)(sW + 32 * u);
            const ULL* wr = (const ULL*)(sW + 32 * (48 + u));
            const ULL* wh = (const ULL*)(sW + 32 * (96 + u));
            ULL az = 0ULL, ar = 0ULL, ah = 0ULL;
            #pragma unroll
            for (int k = 0; k < 16; k++) {
                az = fma2(x2[k], wz[k], az);
                ar = fma2(x2[k], wr[k], ar);
                ah = fma2(x2[k], wh[k], ah);
            }
            float gz = hsum2(az) + sB[u]      + Gp[u];
            float gr = hsum2(ar) + sB[48 + u] + Gp[48 + u];
            float gh = hsum2(ah) + sB[96 + u];
            float z = sigmoidf(gz);
            float r = sigmoidf(gr);
            float hc = tanh_fast(fmaf(r, Gp[96 + u], gh));
            float hprev = hp[u];
            h01[p] = z * hprev + (1.0f - z) * hc;
        }
        hsh[u2 * 96 + tid] = pk2(h01[0], h01[1]);
    }

    // dense head: o = sigmoid( sum_j relu(feat.dot(D[:,j]) + Db[j]) * Ow[j] + Ob )
    float o = sOb;
    for (int j = 0; j < 24; j++) {
        const ULL* dj = (const ULL*)(sD + 80 * j);
        ULL acc = 0ULL;
        #pragma unroll
        for (int k = 0; k < 16; k++) acc = fma2(x2[k], dj[k], acc);
        #pragma unroll
        for (int m = 0; m < 24; m++) acc = fma2(hsh[m * 96 + tid], dj[16 + m], acc);
        float hid = hsum2(acc) + sDb[j];
        hid = fmaxf(hid, 0.0f);
        o = fmaf(hid, sOw[j], o);
    }
    out[b] = sigmoidf(o);

    // last-wins scatter of h_new
    if (g_winner[id] == b) {
        float* os = out_state + id * 48;
        #pragma unroll
        for (int m = 0; m < 24; m++) {
            float2 v = up2(hsh[m * 96 + tid]);
            os[2 * m]     = v.x;
            os[2 * m + 1] = v.y;
        }
    }
}

extern "C" void kernel_launch(void* const* d_in, const int* in_sizes, int n_in,
                              void* d_out, int out_size) {
    const float* inputs = (const float*)d_in[0];
    const int*   ids    = (const int*)d_in[1];
    const float* state  = (const float*)d_in[2];
    const float* Wk     = (const float*)d_in[3];
    const float* Urec   = (const float*)d_in[4];
    const float* gbias  = (const float*)d_in[5];
    const float* Dw     = (const float*)d_in[6];
    const float* Db     = (const float*)d_in[7];
    const float* Ow     = (const float*)d_in[8];
    const float* Ob     = (const float*)d_in[9];

    const int B = in_sizes[0] / 32;
    const int S = in_sizes[2] / 48;

    float* out       = (float*)d_out;
    float* out_state = out + B;

    prep_kernel<<<S, 144>>>(state, Urec, out_state);
    argmax_kernel<<<(B + 255) / 256, 256>>>(ids, B);
    main_kernel<<<(B + 95) / 96, 96>>>(inputs, ids, state, Wk, gbias,
                                       Dw, Db, Ow, Ob, out, out_state, B);
}

// round 2
// speedup vs baseline: 1.5761x; 1.5761x over previous
#include <cuda_runtime.h>
#include <cuda_bf16.h>

// Problem: B=500000, F=32, U=48, S=1000, H=24
// Output: concat( out[B,1], new_state[S,48] ) -> float32

#define ULL unsigned long long

__device__ float g_G[1000 * 144];    // state @ gru_rec_kernel
__device__ int   g_winner[1000];     // last (max) row index per slot
__device__ int   g_count[1000];
__device__ int   g_base[1000];
__device__ int   g_cursor[1000];
__device__ int   g_perm[500000];

// ---------- packed f32x2 helpers ----------
__device__ __forceinline__ ULL pk2(float lo, float hi) {
    ULL r; asm("mov.b64 %0, {%1, %2};" : "=l"(r) : "f"(lo), "f"(hi)); return r;
}
__device__ __forceinline__ float2 up2(ULL v) {
    float2 r; asm("mov.b64 {%0, %1}, %2;" : "=f"(r.x), "=f"(r.y) : "l"(v)); return r;
}
__device__ __forceinline__ ULL fma2(ULL a, ULL b, ULL c) {
    ULL d; asm("fma.rn.f32x2 %0, %1, %2, %3;" : "=l"(d) : "l"(a), "l"(b), "l"(c)); return d;
}
__device__ __forceinline__ float hsum2(ULL v) { float2 f = up2(v); return f.x + f.y; }

__device__ __forceinline__ float sigmoidf(float x) {
    return __fdividef(1.0f, 1.0f + __expf(-x));
}
__device__ __forceinline__ float tanh_fast(float x) {
    return fmaf(2.0f, __fdividef(1.0f, 1.0f + __expf(-2.0f * x)), -1.0f);
}

// ---------- kernel 0: G = state @ U_rec, copy state->out_state, init winner/count ----------
__global__ void prep_kernel(const float* __restrict__ state,
                            const float* __restrict__ Urec,
                            float* __restrict__ out_state) {
    int s = blockIdx.x;
    int j = threadIdx.x;     // 0..143
    __shared__ float hs[48];
    if (j < 48) {
        float v = state[s * 48 + j];
        hs[j] = v;
        out_state[s * 48 + j] = v;
    }
    if (j == 0) { g_winner[s] = -1; g_count[s] = 0; }
    __syncthreads();
    float acc = 0.0f;
    #pragma unroll
    for (int u = 0; u < 48; u++)
        acc = fmaf(hs[u], Urec[u * 144 + j], acc);
    g_G[s * 144 + j] = acc;
}

// ---------- kernel 1: histogram + last-wins winner ----------
__global__ void hist_kernel(const int* __restrict__ ids, int B) {
    int b = blockIdx.x * blockDim.x + threadIdx.x;
    if (b < B) {
        int id = ids[b];
        atomicAdd(&g_count[id], 1);
        atomicMax(&g_winner[id], b);
    }
}

// ---------- kernel 2: exclusive prefix scan over 1000 counts ----------
__global__ void scan_kernel() {
    __shared__ int tmp[1024];
    int t = threadIdx.x;
    int v = (t < 1000) ? g_count[t] : 0;
    tmp[t] = v;
    __syncthreads();
    #pragma unroll
    for (int off = 1; off < 1024; off <<= 1) {
        int u = 0;
        if (t >= off) u = tmp[t - off];
        __syncthreads();
        if (t >= off) tmp[t] += u;
        __syncthreads();
    }
    if (t < 1000) {
        int ex = tmp[t] - v;     // exclusive prefix
        g_base[t] = ex;
        g_cursor[t] = ex;
    }
}

// ---------- kernel 3: scatter row indices into bins ----------
__global__ void scatter_kernel(const int* __restrict__ ids, int B) {
    int b = blockIdx.x * blockDim.x + threadIdx.x;
    if (b < B) {
        int pos = atomicAdd(&g_cursor[ids[b]], 1);
        g_perm[pos] = b;
    }
}

// ---------- kernel 4: main fused GRU + MLP head, binned by slot ----------
#define NCHUNK 4
__global__ void __launch_bounds__(96)
main_kernel(const float* __restrict__ inputs,
            const float* __restrict__ state,
            const float* __restrict__ Wk,      // [32,144]
            const float* __restrict__ gbias,   // [144]
            const float* __restrict__ Dw,      // [80,24]
            const float* __restrict__ Db,      // [24]
            const float* __restrict__ Ow,      // [24]
            const float* __restrict__ Ob,      // [1]
            float* __restrict__ out,           // [B]
            float* __restrict__ out_state) {   // [S,48]
    __shared__ __align__(16) float sW[144 * 32];  // sW[j*32+f] = Wk[f,j]
    __shared__ __align__(16) float sD[24 * 80];   // sD[j*80+c] = Dw[c,j]
    __shared__ float sB[144];
    __shared__ float sG[144];
    __shared__ float sh[48];
    __shared__ float sDb[24];
    __shared__ float sOw[24];
    __shared__ float sOb;
    __shared__ ULL   hsh[24 * 96];                // packed h_new pairs per thread

    const int tid = threadIdx.x;
    const int s     = blockIdx.x >> 2;            // slot
    const int chunk = blockIdx.x & (NCHUNK - 1);  // chunk within slot

    for (int i = tid; i < 144 * 32; i += 96) {
        int j = i >> 5, f = i & 31;
        sW[i] = Wk[f * 144 + j];
    }
    for (int i = tid; i < 24 * 80; i += 96) {
        int j = i / 80, c = i - j * 80;
        sD[i] = Dw[c * 24 + j];
    }
    for (int i = tid; i < 144; i += 96) { sB[i] = gbias[i]; sG[i] = g_G[s * 144 + i]; }
    if (tid < 48) sh[tid] = state[s * 48 + tid];
    if (tid < 24) { sDb[tid] = Db[tid]; sOw[tid] = Ow[tid]; }
    if (tid == 0) sOb = Ob[0];
    __syncthreads();

    const int cnt    = g_count[s];
    const int base   = g_base[s];
    const int winner = g_winner[s];

    for (int i = chunk * 96 + tid; i < cnt; i += NCHUNK * 96) {
        const int b = g_perm[base + i];

        // load x row as 16 packed pairs (full 128B line per row -> no wasted sectors)
        ULL x2[16];
        const float4* xr = (const float4*)(inputs + (size_t)b * 32);
        #pragma unroll
        for (int k = 0; k < 8; k++) {
            float4 v = xr[k];
            x2[2 * k]     = pk2(v.x, v.y);
            x2[2 * k + 1] = pk2(v.z, v.w);
        }

        // GRU units, two at a time -> packed h_new into shared
        for (int u2 = 0; u2 < 24; u2++) {
            float h01[2];
            #pragma unroll
            for (int p = 0; p < 2; p++) {
                const int u = 2 * u2 + p;
                const ulonglong2* wz = (const ulonglong2*)(sW + 32 * u);
                const ulonglong2* wr = (const ulonglong2*)(sW + 32 * (48 + u));
                const ulonglong2* wh = (const ulonglong2*)(sW + 32 * (96 + u));
                ULL az = 0ULL, ar = 0ULL, ah = 0ULL;
                #pragma unroll
                for (int k = 0; k < 8; k++) {
                    ulonglong2 a = wz[k], c = wr[k], e = wh[k];
                    az = fma2(x2[2 * k], a.x, az); az = fma2(x2[2 * k + 1], a.y, az);
                    ar = fma2(x2[2 * k], c.x, ar); ar = fma2(x2[2 * k + 1], c.y, ar);
                    ah = fma2(x2[2 * k], e.x, ah); ah = fma2(x2[2 * k + 1], e.y, ah);
                }
                float gz = hsum2(az) + sB[u]      + sG[u];
                float gr = hsum2(ar) + sB[48 + u] + sG[48 + u];
                float gh = hsum2(ah) + sB[96 + u];
                float z = sigmoidf(gz);
                float r = sigmoidf(gr);
                float hc = tanh_fast(fmaf(r, sG[96 + u], gh));
                float hprev = sh[u];
                h01[p] = z * hprev + (1.0f - z) * hc;
            }
            hsh[u2 * 96 + tid] = pk2(h01[0], h01[1]);
        }

        // dense head
        float o = sOb;
        for (int j = 0; j < 24; j++) {
            const ulonglong2* dj = (const ulonglong2*)(sD + 80 * j);
            ULL acc = 0ULL;
            #pragma unroll
            for (int k = 0; k < 8; k++) {
                ulonglong2 w = dj[k];
                acc = fma2(x2[2 * k], w.x, acc);
                acc = fma2(x2[2 * k + 1], w.y, acc);
            }
            const ULL* djh = (const ULL*)(sD + 80 * j) + 16;
            #pragma unroll
            for (int m = 0; m < 24; m++) acc = fma2(hsh[m * 96 + tid], djh[m], acc);
            float hid = hsum2(acc) + sDb[j];
            hid = fmaxf(hid, 0.0f);
            o = fmaf(hid, sOw[j], o);
        }
        out[b] = sigmoidf(o);

        // last-wins scatter of h_new
        if (b == winner) {
            float* os = out_state + s * 48;
            #pragma unroll
            for (int m = 0; m < 24; m++) {
                float2 v = up2(hsh[m * 96 + tid]);
                os[2 * m]     = v.x;
                os[2 * m + 1] = v.y;
            }
        }
    }
}

extern "C" void kernel_launch(void* const* d_in, const int* in_sizes, int n_in,
                              void* d_out, int out_size) {
    const float* inputs = (const float*)d_in[0];
    const int*   ids    = (const int*)d_in[1];
    const float* state  = (const float*)d_in[2];
    const float* Wk     = (const float*)d_in[3];
    const float* Urec   = (const float*)d_in[4];
    const float* gbias  = (const float*)d_in[5];
    const float* Dw     = (const float*)d_in[6];
    const float* Db     = (const float*)d_in[7];
    const float* Ow     = (const float*)d_in[8];
    const float* Ob     = (const float*)d_in[9];

    const int B = in_sizes[0] / 32;
    const int S = in_sizes[2] / 48;

    float* out       = (float*)d_out;
    float* out_state = out + B;

    prep_kernel<<<S, 144>>>(state, Urec, out_state);
    hist_kernel<<<(B + 255) / 256, 256>>>(ids, B);
    scan_kernel<<<1, 1024>>>();
    scatter_kernel<<<(B + 255) / 256, 256>>>(ids, B);
    main_kernel<<<S * NCHUNK, 96>>>(inputs, state, Wk, gbias,
                                    Dw, Db, Ow, Ob, out, out_state);
}